// round 7
// baseline (speedup 1.0000x reference)
#include <cuda_runtime.h>
#include <cuda_bf16.h>
#include <cstdint>

#define INV_SQRT2 0.70710678118654752440f

#define E_DIM 512
#define A_DIM 128
#define T_DIM 64
#define R_DIM 16
#define MAX_E 100000
#define MAX_ATOMS 5000

// epilogue flags
#define F_ACT  1
#define F_RES  2
#define F_RES2 4
#define F_F32  8
#define F_BF   16
#define F_CMB  32
#define F_RBF  64

// ------------------------------------------------------------------
// Scratch (device globals)
// ------------------------------------------------------------------
__device__ float g_A[(size_t)MAX_E * E_DIM];
__device__ float g_C[(size_t)MAX_E * E_DIM];
__device__ float g_mnew[(size_t)MAX_E * E_DIM];
__device__ float g_rbfW[(size_t)MAX_E * E_DIM];
__device__ float g_upac[(size_t)MAX_E * E_DIM];
__device__ float g_down[(size_t)MAX_E * T_DIM];
__device__ float g_atom[(size_t)MAX_ATOMS * E_DIM];
__device__ float g_atomB[(size_t)MAX_ATOMS * A_DIM];
__device__ float g_atomC[(size_t)MAX_ATOMS * A_DIM];
__device__ float g_hnew[(size_t)MAX_ATOMS * A_DIM];
// bf16 hi/lo ping-pong activation buffers (max width 1024)
__device__ __nv_bfloat16 g_H0h[(size_t)MAX_E * 1024];
__device__ __nv_bfloat16 g_H0l[(size_t)MAX_E * 1024];
__device__ __nv_bfloat16 g_H1h[(size_t)MAX_E * 1024];
__device__ __nv_bfloat16 g_H1l[(size_t)MAX_E * 1024];
// transposed split weights [N][K] (reused serially)
__device__ __nv_bfloat16 g_wBh[1024 * 512];
__device__ __nv_bfloat16 g_wBl[1024 * 512];

// ------------------------------------------------------------------
// Helpers
// ------------------------------------------------------------------
__device__ __forceinline__ float actf(float x) {
    return x * (1.0f / 0.6f) / (1.0f + __expf(-x));
}
__device__ __forceinline__ void split1(float v, __nv_bfloat16& h, __nv_bfloat16& l) {
    h = __float2bfloat16(v);
    l = __float2bfloat16(v - __bfloat162float(h));
}
__device__ __forceinline__ uint32_t smem_u32(const void* p) {
    uint32_t a;
    asm("{ .reg .u64 t; cvta.to.shared.u64 t, %1; cvt.u32.u64 %0, t; }" : "=r"(a) : "l"(p));
    return a;
}
__device__ __forceinline__ void ldm_x4(uint32_t& r0, uint32_t& r1, uint32_t& r2, uint32_t& r3, uint32_t a) {
    asm volatile("ldmatrix.sync.aligned.m8n8.x4.shared.b16 {%0,%1,%2,%3}, [%4];"
                 : "=r"(r0), "=r"(r1), "=r"(r2), "=r"(r3) : "r"(a));
}
__device__ __forceinline__ void mma_bf16(float* c, const uint32_t* a, const uint32_t* b) {
    asm volatile(
        "mma.sync.aligned.m16n8k16.row.col.f32.bf16.bf16.f32 "
        "{%0,%1,%2,%3}, {%4,%5,%6,%7}, {%8,%9}, {%0,%1,%2,%3};"
        : "+f"(c[0]), "+f"(c[1]), "+f"(c[2]), "+f"(c[3])
        : "r"(a[0]), "r"(a[1]), "r"(a[2]), "r"(a[3]), "r"(b[0]), "r"(b[1]));
}
__device__ __forceinline__ void cpa16(uint32_t dst, const void* src) {
    asm volatile("cp.async.cg.shared.global [%0], [%1], 16;" :: "r"(dst), "l"(src));
}
#define CP_COMMIT() asm volatile("cp.async.commit_group;" ::: "memory")
#define CP_WAIT(n)  asm volatile("cp.async.wait_group %0;" :: "n"(n) : "memory")

__device__ __forceinline__ unsigned long long pk2(float v) {
    unsigned long long r;
    unsigned u = __float_as_uint(v);
    asm("mov.b64 %0, {%1, %2};" : "=l"(r) : "r"(u), "r"(u));
    return r;
}
__device__ __forceinline__ void fma2(unsigned long long& a, unsigned long long x, unsigned long long y) {
    asm("fma.rn.f32x2 %0, %1, %2, %0;" : "+l"(a) : "l"(x), "l"(y));
}
__device__ __forceinline__ float2 up2(unsigned long long v) {
    unsigned lo, hi;
    asm("mov.b64 {%0, %1}, %2;" : "=r"(lo), "=r"(hi) : "l"(v));
    return make_float2(__uint_as_float(lo), __uint_as_float(hi));
}

// ------------------------------------------------------------------
// HMMA split-bf16 GEMM with cp.async 2-stage pipeline, 2 CTAs/SM.
// ------------------------------------------------------------------
template <int NT>
__global__ void __launch_bounds__(256, 2) bgemm(
    const __nv_bfloat16* __restrict__ Ah, const __nv_bfloat16* __restrict__ Al,
    const __nv_bfloat16* __restrict__ Bh, const __nv_bfloat16* __restrict__ Bl,
    int M, int Nfull, int K, int flags,
    float* __restrict__ C, const float* __restrict__ res, const float* __restrict__ res2,
    const float* __restrict__ acbuf, const int* __restrict__ swapidx,
    const float* __restrict__ rbfA, const float* __restrict__ rbfW,
    __nv_bfloat16* __restrict__ Ohi, __nv_bfloat16* __restrict__ Olo)
{
    constexpr int BN = NT * 16;
    constexpr int AS_ELE = 128 * 40;
    constexpr int BS_ELE = BN * 40;
    constexpr int STAGE = 2 * AS_ELE + 2 * BS_ELE;
    extern __shared__ __nv_bfloat16 sm[];

    const int tid = threadIdx.x;
    const int lane = tid & 31, wid = tid >> 5;
    const int wm = (wid & 3) * 32;
    const int wn = (wid >> 2) * (NT * 8);
    const long brow = (long)blockIdx.y * 128;
    const long bcol = (long)blockIdx.x * BN;

    float acc[2][NT][4];
#pragma unroll
    for (int i = 0; i < 2; i++)
#pragma unroll
        for (int j = 0; j < NT; j++)
#pragma unroll
            for (int t = 0; t < 4; t++) acc[i][j][t] = 0.f;

    const int nc = K >> 5;

    auto load_chunk = [&](int k0, int s) {
        __nv_bfloat16* Ahs = sm + s * STAGE;
        __nv_bfloat16* Als = Ahs + AS_ELE;
        __nv_bfloat16* Bhs = Als + AS_ELE;
        __nv_bfloat16* Bls = Bhs + BS_ELE;
#pragma unroll
        for (int it = 0; it < 2; it++) {
            int idx = tid + it * 256;
            int r = idx >> 2, j = idx & 3;
            long gr = brow + r;
            if (gr > (long)(M - 1)) gr = M - 1;
            cpa16(smem_u32(Ahs + r * 40 + j * 8), Ah + gr * (long)K + k0 + j * 8);
            cpa16(smem_u32(Als + r * 40 + j * 8), Al + gr * (long)K + k0 + j * 8);
        }
#pragma unroll
        for (int it = 0; it < (BN * 4) / 256; it++) {
            int idx = tid + it * 256;
            int r = idx >> 2, j = idx & 3;
            long gn = bcol + r;
            cpa16(smem_u32(Bhs + r * 40 + j * 8), Bh + gn * (long)K + k0 + j * 8);
            cpa16(smem_u32(Bls + r * 40 + j * 8), Bl + gn * (long)K + k0 + j * 8);
        }
    };

    load_chunk(0, 0);
    CP_COMMIT();

    for (int i = 0; i < nc; i++) {
        if (i + 1 < nc) {
            load_chunk((i + 1) << 5, (i + 1) & 1);
            CP_COMMIT();
            CP_WAIT(1);
        } else {
            CP_WAIT(0);
        }
        __syncthreads();

        const __nv_bfloat16* Ahs = sm + (i & 1) * STAGE;
        const __nv_bfloat16* Als = Ahs + AS_ELE;
        const __nv_bfloat16* Bhs = Als + AS_ELE;
        const __nv_bfloat16* Bls = Bhs + BS_ELE;

#pragma unroll
        for (int ks = 0; ks < 32; ks += 16) {
            uint32_t ah[2][4], al[2][4];
            int arow = lane & 15;
            int acol = ks + ((lane >> 4) << 3);
#pragma unroll
            for (int mt = 0; mt < 2; mt++) {
                uint32_t aaddr = smem_u32(Ahs + (wm + mt * 16 + arow) * 40 + acol);
                ldm_x4(ah[mt][0], ah[mt][1], ah[mt][2], ah[mt][3], aaddr);
                uint32_t laddr = smem_u32(Als + (wm + mt * 16 + arow) * 40 + acol);
                ldm_x4(al[mt][0], al[mt][1], al[mt][2], al[mt][3], laddr);
            }
            int brow_l = (lane & 7) + ((lane >> 4) << 3);
            int bcol_l = ks + (((lane >> 3) & 1) << 3);
#pragma unroll
            for (int ntp = 0; ntp < NT; ntp += 2) {
                uint32_t bh[4], bl[4];
                uint32_t bha = smem_u32(Bhs + (wn + ntp * 8 + brow_l) * 40 + bcol_l);
                ldm_x4(bh[0], bh[1], bh[2], bh[3], bha);
                uint32_t bla = smem_u32(Bls + (wn + ntp * 8 + brow_l) * 40 + bcol_l);
                ldm_x4(bl[0], bl[1], bl[2], bl[3], bla);
#pragma unroll
                for (int mt = 0; mt < 2; mt++) {
                    mma_bf16(acc[mt][ntp], ah[mt], bh);
                    mma_bf16(acc[mt][ntp + 1], ah[mt], bh + 2);
                    mma_bf16(acc[mt][ntp], ah[mt], bl);
                    mma_bf16(acc[mt][ntp + 1], ah[mt], bl + 2);
                    mma_bf16(acc[mt][ntp], al[mt], bh);
                    mma_bf16(acc[mt][ntp + 1], al[mt], bh + 2);
                }
            }
        }
        __syncthreads();
    }

    // ---- optional rbf SMEM tiles (post-mainloop; SMEM reused) ----
    float* srbf = (float*)sm;            // [128][16]
    float* sW   = (float*)sm + 2048;     // [16][BN]
    if (flags & F_RBF) {
        for (int idx = tid; idx < 2048; idx += 256) {
            int r = idx >> 4, t = idx & 15;
            long gr = brow + r;
            if (gr > (long)(M - 1)) gr = M - 1;
            srbf[idx] = rbfA[gr * 16 + t];
        }
        for (int idx = tid; idx < 16 * BN; idx += 256) {
            int t = idx / BN, c = idx - t * BN;
            sW[idx] = rbfW[(long)t * Nfull + bcol + c];
        }
        __syncthreads();
    }

    // ---- epilogue ----
#pragma unroll
    for (int mt = 0; mt < 2; mt++) {
#pragma unroll
        for (int nt = 0; nt < NT; nt++) {
            int lcol = wn + nt * 8 + (lane & 3) * 2;
            long col = bcol + lcol;
#pragma unroll
            for (int half = 0; half < 2; half++) {
                int lrow = wm + mt * 16 + (lane >> 2) + half * 8;
                long row = brow + lrow;
                if (row >= M) continue;
                float vx = acc[mt][nt][half * 2];
                float vy = acc[mt][nt][half * 2 + 1];
                long base = row * (long)Nfull + col;
                if (flags & F_ACT) { vx = actf(vx); vy = actf(vy); }
                if (flags & F_RBF) {
                    float rwx = 0.f, rwy = 0.f;
#pragma unroll
                    for (int t = 0; t < 16; t++) {
                        float rv = srbf[lrow * 16 + t];
                        rwx += rv * sW[t * BN + lcol];
                        rwy += rv * sW[t * BN + lcol + 1];
                    }
                    vx *= rwx; vy *= rwy;
                }
                if (flags & F_CMB) {
                    long sbase = (long)swapidx[row] * Nfull + col;
                    float2 a = *(const float2*)&acbuf[sbase];
                    float2 r = *(const float2*)&res[base];
                    vx = (r.x + (vx + a.x) * INV_SQRT2) * INV_SQRT2;
                    vy = (r.y + (vy + a.y) * INV_SQRT2) * INV_SQRT2;
                }
                if (flags & F_RES) {
                    float2 r = *(const float2*)&res[base];
                    vx = (r.x + vx) * INV_SQRT2;
                    vy = (r.y + vy) * INV_SQRT2;
                }
                if (flags & F_RES2) {
                    float2 r = *(const float2*)&res2[base];
                    vx = (r.x + vx) * INV_SQRT2;
                    vy = (r.y + vy) * INV_SQRT2;
                }
                if (flags & F_F32) *(float2*)&C[base] = make_float2(vx, vy);
                if (flags & F_BF) {
                    __nv_bfloat16 h0, l0, h1, l1;
                    split1(vx, h0, l0); split1(vy, h1, l1);
                    __nv_bfloat162 hp(h0, h1), lp(l0, l1);
                    *(__nv_bfloat162*)&Ohi[base] = hp;
                    *(__nv_bfloat162*)&Olo[base] = lp;
                }
            }
        }
    }
}

// ------------------------------------------------------------------
// Fused triplet + bilinear kernel.
// Block: 16 edges x 32 output-cols (grid.y selects which half of 64).
// SMEM: W_bil half [1024][32] fp32 (128KB), rW [16][1024] fp32 j-major
// (64KB), per-edge staging (12KB). Output: bilinear x -> H1 hi/lo.
// ------------------------------------------------------------------
#define TBIL_SMEM (131072 + 65536 + 16 * (70 + 112 + 10) * 4)

__global__ void __launch_bounds__(256) triplet_bil(
    const float* __restrict__ xd,    // [nE][64]
    const float* __restrict__ sph,   // [nE][10][7]
    const float* __restrict__ cW,    // [nE][16][7]
    const int* __restrict__ ba,      // [nE*10]
    const float* __restrict__ Wb,    // [1024][64]
    int nE,
    __nv_bfloat16* __restrict__ Ohi, __nv_bfloat16* __restrict__ Olo)
{
    extern __shared__ char smraw[];
    float* sWb  = (float*)smraw;                    // [1024][32]
    float* srW  = (float*)(smraw + 131072);         // [16][1024] (j*64+i)
    float* ssph = (float*)(smraw + 131072 + 65536); // [16][70]
    float* scw  = ssph + 16 * 70;                   // [16][112]
    int*   sba  = (int*)(scw + 16 * 112);           // [16][10]

    const int tid = threadIdx.x;
    const int ohalf = blockIdx.y;
    const long e0 = (long)blockIdx.x * 16;

    // ---- phase 0: stage W_bil half ----
    for (int idx = tid; idx < 8192; idx += 256) {
        int ij = idx >> 3, ocq = idx & 7;
        *(float4*)&sWb[ij * 32 + ocq * 4] =
            *(const float4*)&Wb[(long)ij * 64 + ohalf * 32 + ocq * 4];
    }

    // ---- phase 1a: stage per-edge sph/cW/ba (4 groups x 4 rounds) ----
    {
        int g = tid >> 6, t = tid & 63;
#pragma unroll
        for (int r = 0; r < 4; r++) {
            int el = r * 4 + g;
            long eg = e0 + el;
            if (eg < nE) {
                if (t < 10) sba[el * 10 + t] = ba[eg * 10 + t];
                for (int i = t; i < 70; i += 64) ssph[el * 70 + i] = sph[eg * 70 + i];
                for (int i = t; i < 112; i += 64) scw[el * 112 + i] = cW[eg * 112 + i];
            }
        }
    }
    __syncthreads();

    // ---- phase 1b: compute rW into srW (j-major) ----
    {
        int g = tid >> 6, t = tid & 63;
#pragma unroll
        for (int r = 0; r < 4; r++) {
            int el = r * 4 + g;
            long eg = e0 + el;
            if (eg >= nE) continue;
            float xv[10];
#pragma unroll
            for (int k = 0; k < 10; k++)
                xv[k] = xd[(long)sba[el * 10 + k] * 64 + t];
            float sk[7];
#pragma unroll
            for (int s = 0; s < 7; s++) {
                float a = 0.f;
#pragma unroll
                for (int k = 0; k < 10; k++) a += ssph[el * 70 + k * 7 + s] * xv[k];
                sk[s] = a;
            }
#pragma unroll
            for (int j = 0; j < 16; j++) {
                float a = 0.f;
#pragma unroll
                for (int s = 0; s < 7; s++) a += scw[el * 112 + j * 7 + s] * sk[s];
                srW[el * 1024 + j * 64 + t] = a;   // conflict-free (stride-1 in t)
            }
        }
    }
    __syncthreads();

    // ---- phase 2: x[e, o0..o1] = sum_ij rW * Wb ----
    {
        int el = tid >> 4, og = tid & 15;
        long eg = e0 + el;
        if (eg < nE) {
            unsigned long long acc = 0ull;
            const float* rwp = srW + el * 1024;
#pragma unroll
            for (int j = 0; j < 16; j++) {
#pragma unroll
                for (int i4 = 0; i4 < 64; i4 += 4) {
                    float4 rw = *(const float4*)&rwp[j * 64 + i4];
                    unsigned long long w0 = *(const unsigned long long*)&sWb[((i4 + 0) * 16 + j) * 32 + og * 2];
                    unsigned long long w1 = *(const unsigned long long*)&sWb[((i4 + 1) * 16 + j) * 32 + og * 2];
                    unsigned long long w2 = *(const unsigned long long*)&sWb[((i4 + 2) * 16 + j) * 32 + og * 2];
                    unsigned long long w3 = *(const unsigned long long*)&sWb[((i4 + 3) * 16 + j) * 32 + og * 2];
                    fma2(acc, pk2(rw.x), w0);
                    fma2(acc, pk2(rw.y), w1);
                    fma2(acc, pk2(rw.z), w2);
                    fma2(acc, pk2(rw.w), w3);
                }
            }
            float2 v = up2(acc);
            long base = eg * 64 + ohalf * 32 + og * 2;
            __nv_bfloat16 h0, l0, h1, l1;
            split1(v.x, h0, l0); split1(v.y, h1, l1);
            __nv_bfloat162 hp(h0, h1), lp(l0, l1);
            *(__nv_bfloat162*)&Ohi[base] = hp;
            *(__nv_bfloat162*)&Olo[base] = lp;
        }
    }
}

// ------------------------------------------------------------------
// fp32 SGEMM (small GEMMs): C = epi(A @ B)
// ------------------------------------------------------------------
__global__ void __launch_bounds__(256, 2) sgemm_kernel(
    const float* __restrict__ A, const float* __restrict__ B, float* __restrict__ C,
    int M, int N, int K, int flags,
    const float* __restrict__ res)
{
    __shared__ __align__(16) float As[8][128];
    __shared__ __align__(16) float Bs[8][128];
    int tid = threadIdx.x;
    int tx = tid & 15, ty = tid >> 4;
    long brow = (long)blockIdx.y * 128;
    long bcol = (long)blockIdx.x * 128;

    unsigned long long acc[8][4];
#pragma unroll
    for (int i = 0; i < 8; i++)
#pragma unroll
        for (int j = 0; j < 4; j++) acc[i][j] = 0ull;

    int aRow = tid >> 1, aCol = (tid & 1) * 4;
    int bRow = tid >> 5, bCol = (tid & 31) * 4;
    long aGr = brow + aRow;
    long bGc = bcol + bCol;

    for (int k0 = 0; k0 < K; k0 += 8) {
        float4 av = make_float4(0.f, 0.f, 0.f, 0.f);
        if (aGr < M) av = *reinterpret_cast<const float4*>(A + aGr * (long)K + (k0 + aCol));
        As[aCol + 0][aRow] = av.x;
        As[aCol + 1][aRow] = av.y;
        As[aCol + 2][aRow] = av.z;
        As[aCol + 3][aRow] = av.w;
        float4 bv = make_float4(0.f, 0.f, 0.f, 0.f);
        if (bGc < N) bv = *reinterpret_cast<const float4*>(B + (long)(k0 + bRow) * N + bGc);
        *reinterpret_cast<float4*>(&Bs[bRow][bCol]) = bv;
        __syncthreads();
#pragma unroll
        for (int kk = 0; kk < 8; kk++) {
            float4 a0 = *reinterpret_cast<const float4*>(&As[kk][ty * 8]);
            float4 a1 = *reinterpret_cast<const float4*>(&As[kk][ty * 8 + 4]);
            ulonglong2 b0 = *reinterpret_cast<const ulonglong2*>(&Bs[kk][tx * 8]);
            ulonglong2 b1 = *reinterpret_cast<const ulonglong2*>(&Bs[kk][tx * 8 + 4]);
            unsigned long long bb[4] = {b0.x, b0.y, b1.x, b1.y};
            float ra[8] = {a0.x, a0.y, a0.z, a0.w, a1.x, a1.y, a1.z, a1.w};
#pragma unroll
            for (int i = 0; i < 8; i++) {
                unsigned long long a2 = pk2(ra[i]);
#pragma unroll
                for (int j = 0; j < 4; j++) fma2(acc[i][j], a2, bb[j]);
            }
        }
        __syncthreads();
    }

#pragma unroll
    for (int i = 0; i < 8; i++) {
        long row = brow + ty * 8 + i;
        if (row >= M) continue;
#pragma unroll
        for (int j = 0; j < 4; j++) {
            long col = bcol + tx * 8 + j * 2;
            if (col >= N) continue;
            float2 v = up2(acc[i][j]);
            long idx = row * (long)N + col;
            if (flags & F_ACT) { v.x = actf(v.x); v.y = actf(v.y); }
            if (flags & F_RES) {
                v.x = (res[idx] + v.x) * INV_SQRT2;
                v.y = (res[idx + 1] + v.y) * INV_SQRT2;
            }
            C[idx] = v.x;
            C[idx + 1] = v.y;
        }
    }
}

// ------------------------------------------------------------------
// Conversions
// ------------------------------------------------------------------
__global__ void convertA_kernel(const float* __restrict__ x,
                                __nv_bfloat16* __restrict__ hi, __nv_bfloat16* __restrict__ lo, long n)
{
    long i = (long)blockIdx.x * blockDim.x + threadIdx.x;
    if (i >= n) return;
    __nv_bfloat16 h, l;
    split1(x[i], h, l);
    hi[i] = h; lo[i] = l;
}

__global__ void convertW_kernel(const float* __restrict__ W,
                                __nv_bfloat16* __restrict__ hi, __nv_bfloat16* __restrict__ lo,
                                int K, int N)
{
    long i = (long)blockIdx.x * blockDim.x + threadIdx.x;
    long tot = (long)K * N;
    if (i >= tot) return;
    int n = (int)(i / K), k = (int)(i - (long)n * K);
    __nv_bfloat16 h, l;
    split1(W[(long)k * N + n], h, l);
    hi[i] = h; lo[i] = l;
}

// ------------------------------------------------------------------
// Remaining elementwise kernels
// ------------------------------------------------------------------
__global__ void zero_kernel(float* __restrict__ p, long n)
{
    long i = (long)blockIdx.x * blockDim.x + threadIdx.x;
    if (i < n) p[i] = 0.f;
}

__global__ void scatter_kernel(const float* __restrict__ mnew, const float* __restrict__ rw,
                               const int* __restrict__ id_a, float* __restrict__ atom, int nE)
{
    long i = (long)blockIdx.x * blockDim.x + threadIdx.x;
    long n = (long)nE * E_DIM;
    if (i >= n) return;
    long e = i >> 9;
    int c = (int)(i & 511);
    atomicAdd(&atom[(long)id_a[e] * E_DIM + c], mnew[i] * rw[i]);
}

__global__ void hnew_kernel(const float* __restrict__ h, const float* __restrict__ xa,
                            float* __restrict__ hnew, float* __restrict__ out, long n)
{
    long i = (long)blockIdx.x * blockDim.x + threadIdx.x;
    if (i >= n) return;
    float v = (h[i] + xa[i]) * INV_SQRT2;
    hnew[i] = v;
    out[i] = v;
}

__global__ void concat_kernel(const float* __restrict__ hnew, const int* __restrict__ id_c,
                              const int* __restrict__ id_a, const float* __restrict__ mnew,
                              __nv_bfloat16* __restrict__ ohi, __nv_bfloat16* __restrict__ olo, int nE)
{
    long i = (long)blockIdx.x * blockDim.x + threadIdx.x;
    long n = (long)nE * 768;
    if (i >= n) return;
    long e = i / 768;
    int k = (int)(i - e * 768);
    float v;
    if (k < 128)      v = hnew[(long)id_c[e] * A_DIM + k];
    else if (k < 256) v = hnew[(long)id_a[e] * A_DIM + (k - 128)];
    else              v = mnew[e * (long)E_DIM + (k - 256)];
    __nv_bfloat16 h, l; split1(v, h, l);
    ohi[i] = h; olo[i] = l;
}

// ------------------------------------------------------------------
// Host orchestration
// ------------------------------------------------------------------
static inline void sg(const float* A, const float* B, float* C, int M, int N, int K,
                      int flags, const float* res = nullptr)
{
    dim3 grid((N + 127) / 128, (M + 127) / 128);
    sgemm_kernel<<<grid, 256>>>(A, B, C, M, N, K, flags, res);
}

#define SMEM8 ((2 * 128 * 40 + 2 * 128 * 40) * 2 * 2)  // 81920 B
#define SMEM4 ((2 * 128 * 40 + 2 * 64 * 40) * 2 * 2)   // 61440 B

extern "C" void kernel_launch(void* const* d_in, const int* in_sizes, int n_in,
                              void* d_out, int out_size)
{
    const float* h_in       = (const float*)d_in[0];
    const float* m_in       = (const float*)d_in[1];
    const float* rbf3       = (const float*)d_in[2];
    const float* cbfW1      = (const float*)d_in[3];
    const float* sph        = (const float*)d_in[4];
    const float* rbf_h      = (const float*)d_in[5];
    const float* W_dense_ca = (const float*)d_in[6];
    const float* W_ba       = (const float*)d_in[7];
    const float* W_rbf3     = (const float*)d_in[8];
    const float* W_down     = (const float*)d_in[9];
    const float* W_bil      = (const float*)d_in[10];
    const float* W_up_ca    = (const float*)d_in[11];
    const float* W_up_ac    = (const float*)d_in[12];
    const float* W_res_b    = (const float*)d_in[13];
    const float* W_res_a    = (const float*)d_in[14];
    const float* W_rbf_hW   = (const float*)d_in[15];
    const float* W_atom_d   = (const float*)d_in[16];
    const float* W_atom_r   = (const float*)d_in[17];
    const float* W_concat   = (const float*)d_in[18];
    const float* W_res_m    = (const float*)d_in[19];
    const int* id_swap = (const int*)d_in[21];
    const int* id3_ba  = (const int*)d_in[22];
    const int* id_c    = (const int*)d_in[24];
    const int* id_a    = (const int*)d_in[25];

    int nE = in_sizes[1] / E_DIM;
    int nA = in_sizes[0] / A_DIM;
    float* out = (float*)d_out;

    float *pA, *pC, *pmnew, *prbfW, *pupac, *pdown;
    float *patom, *patomB, *patomC, *phnew;
    __nv_bfloat16 *H0h, *H0l, *H1h, *H1l, *wBh, *wBl;
    cudaGetSymbolAddress((void**)&pA, g_A);
    cudaGetSymbolAddress((void**)&pC, g_C);
    cudaGetSymbolAddress((void**)&pmnew, g_mnew);
    cudaGetSymbolAddress((void**)&prbfW, g_rbfW);
    cudaGetSymbolAddress((void**)&pupac, g_upac);
    cudaGetSymbolAddress((void**)&pdown, g_down);
    cudaGetSymbolAddress((void**)&patom, g_atom);
    cudaGetSymbolAddress((void**)&patomB, g_atomB);
    cudaGetSymbolAddress((void**)&patomC, g_atomC);
    cudaGetSymbolAddress((void**)&phnew, g_hnew);
    cudaGetSymbolAddress((void**)&H0h, g_H0h);
    cudaGetSymbolAddress((void**)&H0l, g_H0l);
    cudaGetSymbolAddress((void**)&H1h, g_H1h);
    cudaGetSymbolAddress((void**)&H1l, g_H1l);
    cudaGetSymbolAddress((void**)&wBh, g_wBh);
    cudaGetSymbolAddress((void**)&wBl, g_wBl);

    cudaFuncSetAttribute(bgemm<8>, cudaFuncAttributeMaxDynamicSharedMemorySize, SMEM8);
    cudaFuncSetAttribute(bgemm<4>, cudaFuncAttributeMaxDynamicSharedMemorySize, SMEM4);
    cudaFuncSetAttribute(triplet_bil, cudaFuncAttributeMaxDynamicSharedMemorySize, TBIL_SMEM);

    long nME = (long)nE * E_DIM;
    int TB = 256;
    long gME = (nME + TB - 1) / TB;

    auto convW = [&](const float* W, int K, int N) {
        long n = (long)K * N;
        convertW_kernel<<<(unsigned)((n + 255) / 256), 256>>>(W, wBh, wBl, K, N);
    };
    auto tc128 = [&](const __nv_bfloat16* Ahp, const __nv_bfloat16* Alp, int M, int Nf, int K,
                     int flags, float* C, const float* res, const float* res2,
                     const float* acbuf, const int* swapidx,
                     const float* rbfA, const float* rbfWp,
                     __nv_bfloat16* Oh, __nv_bfloat16* Ol) {
        dim3 grid(Nf / 128, (M + 127) / 128);
        bgemm<8><<<grid, 256, SMEM8>>>(Ahp, Alp, wBh, wBl, M, Nf, K, flags, C, res, res2,
                                       acbuf, swapidx, rbfA, rbfWp, Oh, Ol);
    };
    auto tc64 = [&](const __nv_bfloat16* Ahp, const __nv_bfloat16* Alp, int M, int Nf, int K,
                    int flags, float* C, __nv_bfloat16* Oh, __nv_bfloat16* Ol) {
        dim3 grid(Nf / 64, (M + 127) / 128);
        bgemm<4><<<grid, 256, SMEM4>>>(Ahp, Alp, wBh, wBl, M, Nf, K, flags, C, nullptr, nullptr,
                                       nullptr, nullptr, nullptr, nullptr, Oh, Ol);
    };

    // ---- m -> H0 hi/lo ----
    convertA_kernel<<<(unsigned)gME, TB>>>(m_in, H0h, H0l, nME);
    // ---- skip branch -> pA ----
    convW(W_dense_ca, 512, 512);
    tc128(H0h, H0l, nE, 512, 512, F_ACT | F_F32, pA, nullptr, nullptr, nullptr, nullptr,
          nullptr, nullptr, nullptr, nullptr);
    // ---- x_ba = act(m@W_ba) * (rbf3@W_rbf3) -> H1 (rbf MLP fused) ----
    convW(W_ba, 512, 512);
    tc128(H0h, H0l, nE, 512, 512, F_ACT | F_RBF | F_BF, nullptr, nullptr, nullptr, nullptr,
          nullptr, rbf3, W_rbf3, H1h, H1l);
    // ---- down ----
    convW(W_down, 512, 64);
    tc64(H1h, H1l, nE, 64, 512, F_ACT | F_F32, pdown, nullptr, nullptr);
    // ---- fused triplet + bilinear -> H1 (width 64, exact fp32 bilinear) ----
    {
        dim3 grid((nE + 15) / 16, 2);
        triplet_bil<<<grid, 256, TBIL_SMEM>>>(pdown, sph, cbfW1, id3_ba, W_bil, nE, H1h, H1l);
    }
    // ---- up_ac (must precede fused combine) ----
    convW(W_up_ac, 64, 512);
    tc128(H1h, H1l, nE, 512, 64, F_ACT | F_F32, pupac, nullptr, nullptr, nullptr, nullptr,
          nullptr, nullptr, nullptr, nullptr);
    // ---- up_ca with fused combine -> pC + H0 ----
    convW(W_up_ca, 64, 512);
    tc128(H1h, H1l, nE, 512, 64, F_ACT | F_CMB | F_F32 | F_BF, pC, pA, nullptr, pupac, id_swap,
          nullptr, nullptr, H0h, H0l);
    // ---- residual before; 2nd GEMM fuses m_new = (m + (pC + act)*s)*s ----
    convW(W_res_b, 512, 512);
    tc128(H0h, H0l, nE, 512, 512, F_ACT | F_BF, nullptr, nullptr, nullptr, nullptr, nullptr,
          nullptr, nullptr, H1h, H1l);
    convW(W_res_b + 262144, 512, 512);
    tc128(H1h, H1l, nE, 512, 512, F_ACT | F_RES | F_RES2 | F_F32 | F_BF, pmnew, pC, m_in,
          nullptr, nullptr, nullptr, nullptr, H0h, H0l);
    // ---- residual after x2 ----
    for (int i = 0; i < 2; i++) {
        convW(W_res_a + (long)i * 2 * 262144, 512, 512);
        tc128(H0h, H0l, nE, 512, 512, F_ACT | F_BF, nullptr, nullptr, nullptr, nullptr, nullptr,
              nullptr, nullptr, H1h, H1l);
        convW(W_res_a + (long)i * 2 * 262144 + 262144, 512, 512);
        tc128(H1h, H1l, nE, 512, 512, F_ACT | F_RES | F_F32 | F_BF, pmnew, pmnew, nullptr,
              nullptr, nullptr, nullptr, nullptr, H0h, H0l);
    }
    // ---- atom update (fp32 path) ----
    sg(rbf_h, W_rbf_hW, prbfW, nE, E_DIM, R_DIM, 0);
    long nAtomE = (long)nA * E_DIM;
    zero_kernel<<<(unsigned)((nAtomE + TB - 1) / TB), TB>>>(patom, nAtomE);
    scatter_kernel<<<(unsigned)gME, TB>>>(pmnew, prbfW, id_a, patom, nE);
    sg(patom, W_atom_d, patomB, nA, A_DIM, E_DIM, F_ACT);
    for (int i = 0; i < 3; i++) {
        sg(patomB, W_atom_r + (long)i * 2 * 16384, patomC, nA, A_DIM, A_DIM, F_ACT);
        sg(patomC, W_atom_r + (long)i * 2 * 16384 + 16384, patomB, nA, A_DIM, A_DIM,
           F_ACT | F_RES, patomB);
    }
    long nAA = (long)nA * A_DIM;
    hnew_kernel<<<(unsigned)((nAA + TB - 1) / TB), TB>>>(h_in, patomB, phnew, out, nAA);
    // ---- edge embedding ----
    long nCE = (long)nE * 768;
    concat_kernel<<<(unsigned)((nCE + TB - 1) / TB), TB>>>(phnew, id_c, id_a, pmnew, H1h, H1l, nE);
    convW(W_concat, 768, 512);
    tc128(H1h, H1l, nE, 512, 768, F_ACT | F_F32 | F_BF, pA, nullptr, nullptr, nullptr, nullptr,
          nullptr, nullptr, H0h, H0l);
    convW(W_res_m, 512, 512);
    tc128(H0h, H0l, nE, 512, 512, F_ACT | F_BF, nullptr, nullptr, nullptr, nullptr, nullptr,
          nullptr, nullptr, H1h, H1l);
    // ---- last GEMM fuses m_out = (mnew + (pA + act)*s)*s -> out ----
    convW(W_res_m + 262144, 512, 512);
    tc128(H1h, H1l, nE, 512, 512, F_ACT | F_RES | F_RES2 | F_F32, out + nAA, pA, pmnew,
          nullptr, nullptr, nullptr, nullptr, nullptr, nullptr);
}

// round 9
// speedup vs baseline: 1.1010x; 1.1010x over previous
#include <cuda_runtime.h>
#include <cuda_bf16.h>
#include <cstdint>

#define INV_SQRT2 0.70710678118654752440f

#define E_DIM 512
#define A_DIM 128
#define T_DIM 64
#define R_DIM 16
#define MAX_E 100000
#define MAX_ATOMS 5000

// epilogue flags
#define F_ACT  1
#define F_RES  2
#define F_RES2 4
#define F_F32  8
#define F_BF   16
#define F_CMB  32
#define F_RBF  64

// ------------------------------------------------------------------
// Scratch (device globals)
// ------------------------------------------------------------------
__device__ float g_A[(size_t)MAX_E * E_DIM];
__device__ float g_C[(size_t)MAX_E * E_DIM];
__device__ float g_mnew[(size_t)MAX_E * E_DIM];
__device__ float g_upac[(size_t)MAX_E * E_DIM];
__device__ float g_down[(size_t)MAX_E * T_DIM];
__device__ float g_atom[(size_t)MAX_ATOMS * E_DIM];
__device__ float g_atomB[(size_t)MAX_ATOMS * A_DIM];
__device__ float g_atomC[(size_t)MAX_ATOMS * A_DIM];
__device__ float g_hnew[(size_t)MAX_ATOMS * A_DIM];
// bf16 hi/lo ping-pong activation buffers (max width 1024)
__device__ __nv_bfloat16 g_H0h[(size_t)MAX_E * 1024];
__device__ __nv_bfloat16 g_H0l[(size_t)MAX_E * 1024];
__device__ __nv_bfloat16 g_H1h[(size_t)MAX_E * 1024];
__device__ __nv_bfloat16 g_H1l[(size_t)MAX_E * 1024];
// transposed split weights [N][K] (reused serially)
__device__ __nv_bfloat16 g_wBh[1024 * 512];
__device__ __nv_bfloat16 g_wBl[1024 * 512];

// ------------------------------------------------------------------
// Helpers
// ------------------------------------------------------------------
__device__ __forceinline__ float actf(float x) {
    return x * (1.0f / 0.6f) / (1.0f + __expf(-x));
}
__device__ __forceinline__ void split1(float v, __nv_bfloat16& h, __nv_bfloat16& l) {
    h = __float2bfloat16(v);
    l = __float2bfloat16(v - __bfloat162float(h));
}
__device__ __forceinline__ uint32_t smem_u32(const void* p) {
    uint32_t a;
    asm("{ .reg .u64 t; cvta.to.shared.u64 t, %1; cvt.u32.u64 %0, t; }" : "=r"(a) : "l"(p));
    return a;
}
__device__ __forceinline__ void ldm_x4(uint32_t& r0, uint32_t& r1, uint32_t& r2, uint32_t& r3, uint32_t a) {
    asm volatile("ldmatrix.sync.aligned.m8n8.x4.shared.b16 {%0,%1,%2,%3}, [%4];"
                 : "=r"(r0), "=r"(r1), "=r"(r2), "=r"(r3) : "r"(a));
}
__device__ __forceinline__ void mma_bf16(float* c, const uint32_t* a, const uint32_t* b) {
    asm volatile(
        "mma.sync.aligned.m16n8k16.row.col.f32.bf16.bf16.f32 "
        "{%0,%1,%2,%3}, {%4,%5,%6,%7}, {%8,%9}, {%0,%1,%2,%3};"
        : "+f"(c[0]), "+f"(c[1]), "+f"(c[2]), "+f"(c[3])
        : "r"(a[0]), "r"(a[1]), "r"(a[2]), "r"(a[3]), "r"(b[0]), "r"(b[1]));
}
__device__ __forceinline__ void cpa16(uint32_t dst, const void* src) {
    asm volatile("cp.async.cg.shared.global [%0], [%1], 16;" :: "r"(dst), "l"(src));
}
#define CP_COMMIT() asm volatile("cp.async.commit_group;" ::: "memory")
#define CP_WAIT(n)  asm volatile("cp.async.wait_group %0;" :: "n"(n) : "memory")

__device__ __forceinline__ unsigned long long pk2(float v) {
    unsigned long long r;
    unsigned u = __float_as_uint(v);
    asm("mov.b64 %0, {%1, %2};" : "=l"(r) : "r"(u), "r"(u));
    return r;
}
__device__ __forceinline__ void fma2(unsigned long long& a, unsigned long long x, unsigned long long y) {
    asm("fma.rn.f32x2 %0, %1, %2, %0;" : "+l"(a) : "l"(x), "l"(y));
}
__device__ __forceinline__ float2 up2(unsigned long long v) {
    unsigned lo, hi;
    asm("mov.b64 {%0, %1}, %2;" : "=r"(lo), "=r"(hi) : "l"(v));
    return make_float2(__uint_as_float(lo), __uint_as_float(hi));
}

// ------------------------------------------------------------------
// HMMA split-bf16 GEMM with cp.async 2-stage pipeline, 2 CTAs/SM.
// ------------------------------------------------------------------
template <int NT>
__global__ void __launch_bounds__(256, 2) bgemm(
    const __nv_bfloat16* __restrict__ Ah, const __nv_bfloat16* __restrict__ Al,
    const __nv_bfloat16* __restrict__ Bh, const __nv_bfloat16* __restrict__ Bl,
    int M, int Nfull, int K, int flags,
    float* __restrict__ C, const float* __restrict__ res, const float* __restrict__ res2,
    const float* __restrict__ acbuf, const int* __restrict__ swapidx,
    const float* __restrict__ rbfA, const float* __restrict__ rbfW,
    __nv_bfloat16* __restrict__ Ohi, __nv_bfloat16* __restrict__ Olo)
{
    constexpr int BN = NT * 16;
    constexpr int AS_ELE = 128 * 40;
    constexpr int BS_ELE = BN * 40;
    constexpr int STAGE = 2 * AS_ELE + 2 * BS_ELE;
    extern __shared__ __nv_bfloat16 sm[];

    const int tid = threadIdx.x;
    const int lane = tid & 31, wid = tid >> 5;
    const int wm = (wid & 3) * 32;
    const int wn = (wid >> 2) * (NT * 8);
    const long brow = (long)blockIdx.y * 128;
    const long bcol = (long)blockIdx.x * BN;

    float acc[2][NT][4];
#pragma unroll
    for (int i = 0; i < 2; i++)
#pragma unroll
        for (int j = 0; j < NT; j++)
#pragma unroll
            for (int t = 0; t < 4; t++) acc[i][j][t] = 0.f;

    const int nc = K >> 5;

    auto load_chunk = [&](int k0, int s) {
        __nv_bfloat16* Ahs = sm + s * STAGE;
        __nv_bfloat16* Als = Ahs + AS_ELE;
        __nv_bfloat16* Bhs = Als + AS_ELE;
        __nv_bfloat16* Bls = Bhs + BS_ELE;
#pragma unroll
        for (int it = 0; it < 2; it++) {
            int idx = tid + it * 256;
            int r = idx >> 2, j = idx & 3;
            long gr = brow + r;
            if (gr > (long)(M - 1)) gr = M - 1;
            cpa16(smem_u32(Ahs + r * 40 + j * 8), Ah + gr * (long)K + k0 + j * 8);
            cpa16(smem_u32(Als + r * 40 + j * 8), Al + gr * (long)K + k0 + j * 8);
        }
#pragma unroll
        for (int it = 0; it < (BN * 4) / 256; it++) {
            int idx = tid + it * 256;
            int r = idx >> 2, j = idx & 3;
            long gn = bcol + r;
            cpa16(smem_u32(Bhs + r * 40 + j * 8), Bh + gn * (long)K + k0 + j * 8);
            cpa16(smem_u32(Bls + r * 40 + j * 8), Bl + gn * (long)K + k0 + j * 8);
        }
    };

    load_chunk(0, 0);
    CP_COMMIT();

    for (int i = 0; i < nc; i++) {
        if (i + 1 < nc) {
            load_chunk((i + 1) << 5, (i + 1) & 1);
            CP_COMMIT();
            CP_WAIT(1);
        } else {
            CP_WAIT(0);
        }
        __syncthreads();

        const __nv_bfloat16* Ahs = sm + (i & 1) * STAGE;
        const __nv_bfloat16* Als = Ahs + AS_ELE;
        const __nv_bfloat16* Bhs = Als + AS_ELE;
        const __nv_bfloat16* Bls = Bhs + BS_ELE;

#pragma unroll
        for (int ks = 0; ks < 32; ks += 16) {
            uint32_t ah[2][4], al[2][4];
            int arow = lane & 15;
            int acol = ks + ((lane >> 4) << 3);
#pragma unroll
            for (int mt = 0; mt < 2; mt++) {
                uint32_t aaddr = smem_u32(Ahs + (wm + mt * 16 + arow) * 40 + acol);
                ldm_x4(ah[mt][0], ah[mt][1], ah[mt][2], ah[mt][3], aaddr);
                uint32_t laddr = smem_u32(Als + (wm + mt * 16 + arow) * 40 + acol);
                ldm_x4(al[mt][0], al[mt][1], al[mt][2], al[mt][3], laddr);
            }
            int brow_l = (lane & 7) + ((lane >> 4) << 3);
            int bcol_l = ks + (((lane >> 3) & 1) << 3);
#pragma unroll
            for (int ntp = 0; ntp < NT; ntp += 2) {
                uint32_t bh[4], bl[4];
                uint32_t bha = smem_u32(Bhs + (wn + ntp * 8 + brow_l) * 40 + bcol_l);
                ldm_x4(bh[0], bh[1], bh[2], bh[3], bha);
                uint32_t bla = smem_u32(Bls + (wn + ntp * 8 + brow_l) * 40 + bcol_l);
                ldm_x4(bl[0], bl[1], bl[2], bl[3], bla);
#pragma unroll
                for (int mt = 0; mt < 2; mt++) {
                    mma_bf16(acc[mt][ntp], ah[mt], bh);
                    mma_bf16(acc[mt][ntp + 1], ah[mt], bh + 2);
                    mma_bf16(acc[mt][ntp], ah[mt], bl);
                    mma_bf16(acc[mt][ntp + 1], ah[mt], bl + 2);
                    mma_bf16(acc[mt][ntp], al[mt], bh);
                    mma_bf16(acc[mt][ntp + 1], al[mt], bh + 2);
                }
            }
        }
        __syncthreads();
    }

    // ---- optional rbf SMEM tiles (post-mainloop; SMEM reused) ----
    float* srbf = (float*)sm;            // [128][16]
    float* sW   = (float*)sm + 2048;     // [16][BN]
    if (flags & F_RBF) {
        for (int idx = tid; idx < 2048; idx += 256) {
            int r = idx >> 4, t = idx & 15;
            long gr = brow + r;
            if (gr > (long)(M - 1)) gr = M - 1;
            srbf[idx] = rbfA[gr * 16 + t];
        }
        for (int idx = tid; idx < 16 * BN; idx += 256) {
            int t = idx / BN, c = idx - t * BN;
            sW[idx] = rbfW[(long)t * Nfull + bcol + c];
        }
        __syncthreads();
    }

    // ---- epilogue ----
#pragma unroll
    for (int mt = 0; mt < 2; mt++) {
#pragma unroll
        for (int nt = 0; nt < NT; nt++) {
            int lcol = wn + nt * 8 + (lane & 3) * 2;
            long col = bcol + lcol;
#pragma unroll
            for (int half = 0; half < 2; half++) {
                int lrow = wm + mt * 16 + (lane >> 2) + half * 8;
                long row = brow + lrow;
                if (row >= M) continue;
                float vx = acc[mt][nt][half * 2];
                float vy = acc[mt][nt][half * 2 + 1];
                long base = row * (long)Nfull + col;
                if (flags & F_ACT) { vx = actf(vx); vy = actf(vy); }
                if (flags & F_RBF) {
                    float rwx = 0.f, rwy = 0.f;
#pragma unroll
                    for (int t = 0; t < 16; t++) {
                        float rv = srbf[lrow * 16 + t];
                        rwx += rv * sW[t * BN + lcol];
                        rwy += rv * sW[t * BN + lcol + 1];
                    }
                    vx *= rwx; vy *= rwy;
                }
                if (flags & F_CMB) {
                    long sbase = (long)swapidx[row] * Nfull + col;
                    float2 a = *(const float2*)&acbuf[sbase];
                    float2 r = *(const float2*)&res[base];
                    vx = (r.x + (vx + a.x) * INV_SQRT2) * INV_SQRT2;
                    vy = (r.y + (vy + a.y) * INV_SQRT2) * INV_SQRT2;
                }
                if (flags & F_RES) {
                    float2 r = *(const float2*)&res[base];
                    vx = (r.x + vx) * INV_SQRT2;
                    vy = (r.y + vy) * INV_SQRT2;
                }
                if (flags & F_RES2) {
                    float2 r = *(const float2*)&res2[base];
                    vx = (r.x + vx) * INV_SQRT2;
                    vy = (r.y + vy) * INV_SQRT2;
                }
                if (flags & F_F32) *(float2*)&C[base] = make_float2(vx, vy);
                if (flags & F_BF) {
                    __nv_bfloat16 h0, l0, h1, l1;
                    split1(vx, h0, l0); split1(vy, h1, l1);
                    __nv_bfloat162 hp(h0, h1), lp(l0, l1);
                    *(__nv_bfloat162*)&Ohi[base] = hp;
                    *(__nv_bfloat162*)&Olo[base] = lp;
                }
            }
        }
    }
}

// ------------------------------------------------------------------
// fp32 SGEMM (small GEMMs): C = epi(A @ B)
// ------------------------------------------------------------------
__global__ void __launch_bounds__(256, 2) sgemm_kernel(
    const float* __restrict__ A, const float* __restrict__ B, float* __restrict__ C,
    int M, int N, int K, int flags,
    const float* __restrict__ res)
{
    __shared__ __align__(16) float As[8][128];
    __shared__ __align__(16) float Bs[8][128];
    int tid = threadIdx.x;
    int tx = tid & 15, ty = tid >> 4;
    long brow = (long)blockIdx.y * 128;
    long bcol = (long)blockIdx.x * 128;

    unsigned long long acc[8][4];
#pragma unroll
    for (int i = 0; i < 8; i++)
#pragma unroll
        for (int j = 0; j < 4; j++) acc[i][j] = 0ull;

    int aRow = tid >> 1, aCol = (tid & 1) * 4;
    int bRow = tid >> 5, bCol = (tid & 31) * 4;
    long aGr = brow + aRow;
    long bGc = bcol + bCol;

    for (int k0 = 0; k0 < K; k0 += 8) {
        float4 av = make_float4(0.f, 0.f, 0.f, 0.f);
        if (aGr < M) av = *reinterpret_cast<const float4*>(A + aGr * (long)K + (k0 + aCol));
        As[aCol + 0][aRow] = av.x;
        As[aCol + 1][aRow] = av.y;
        As[aCol + 2][aRow] = av.z;
        As[aCol + 3][aRow] = av.w;
        float4 bv = make_float4(0.f, 0.f, 0.f, 0.f);
        if (bGc < N) bv = *reinterpret_cast<const float4*>(B + (long)(k0 + bRow) * N + bGc);
        *reinterpret_cast<float4*>(&Bs[bRow][bCol]) = bv;
        __syncthreads();
#pragma unroll
        for (int kk = 0; kk < 8; kk++) {
            float4 a0 = *reinterpret_cast<const float4*>(&As[kk][ty * 8]);
            float4 a1 = *reinterpret_cast<const float4*>(&As[kk][ty * 8 + 4]);
            ulonglong2 b0 = *reinterpret_cast<const ulonglong2*>(&Bs[kk][tx * 8]);
            ulonglong2 b1 = *reinterpret_cast<const ulonglong2*>(&Bs[kk][tx * 8 + 4]);
            unsigned long long bb[4] = {b0.x, b0.y, b1.x, b1.y};
            float ra[8] = {a0.x, a0.y, a0.z, a0.w, a1.x, a1.y, a1.z, a1.w};
#pragma unroll
            for (int i = 0; i < 8; i++) {
                unsigned long long a2 = pk2(ra[i]);
#pragma unroll
                for (int j = 0; j < 4; j++) fma2(acc[i][j], a2, bb[j]);
            }
        }
        __syncthreads();
    }

#pragma unroll
    for (int i = 0; i < 8; i++) {
        long row = brow + ty * 8 + i;
        if (row >= M) continue;
#pragma unroll
        for (int j = 0; j < 4; j++) {
            long col = bcol + tx * 8 + j * 2;
            if (col >= N) continue;
            float2 v = up2(acc[i][j]);
            long idx = row * (long)N + col;
            if (flags & F_ACT) { v.x = actf(v.x); v.y = actf(v.y); }
            if (flags & F_RES) {
                v.x = (res[idx] + v.x) * INV_SQRT2;
                v.y = (res[idx + 1] + v.y) * INV_SQRT2;
            }
            C[idx] = v.x;
            C[idx + 1] = v.y;
        }
    }
}

// ------------------------------------------------------------------
// Conversions
// ------------------------------------------------------------------
__global__ void convertA_kernel(const float* __restrict__ x,
                                __nv_bfloat16* __restrict__ hi, __nv_bfloat16* __restrict__ lo, long n)
{
    long i = (long)blockIdx.x * blockDim.x + threadIdx.x;
    if (i >= n) return;
    __nv_bfloat16 h, l;
    split1(x[i], h, l);
    hi[i] = h; lo[i] = l;
}

__global__ void convertW_kernel(const float* __restrict__ W,
                                __nv_bfloat16* __restrict__ hi, __nv_bfloat16* __restrict__ lo,
                                int K, int N)
{
    long i = (long)blockIdx.x * blockDim.x + threadIdx.x;
    long tot = (long)K * N;
    if (i >= tot) return;
    int n = (int)(i / K), k = (int)(i - (long)n * K);
    __nv_bfloat16 h, l;
    split1(W[(long)k * N + n], h, l);
    hi[i] = h; lo[i] = l;
}

// ------------------------------------------------------------------
// Triplet kernel: emits rW as bf16 hi/lo [(e), (i*16+j)]
// ------------------------------------------------------------------
__global__ void triplet_kernel(
    const float* __restrict__ xd, const float* __restrict__ sph,
    const float* __restrict__ cW, const int* __restrict__ ba,
    __nv_bfloat16* __restrict__ rWh, __nv_bfloat16* __restrict__ rWl, int nE)
{
    int e = blockIdx.x;
    if (e >= nE) return;
    int t = threadIdx.x;

    __shared__ float s_xd[10][64];
    __shared__ float s_sph[70];
    __shared__ float s_cW[112];
    __shared__ int s_ba[10];

    if (t < 10) s_ba[t] = ba[e * 10 + t];
    for (int i = t; i < 70; i += 64) s_sph[i] = sph[(long)e * 70 + i];
    for (int i = t; i < 112; i += 64) s_cW[i] = cW[(long)e * 112 + i];
    __syncthreads();
#pragma unroll
    for (int k = 0; k < 10; k++) s_xd[k][t] = xd[(long)s_ba[k] * 64 + t];
    __syncthreads();

    float sk[7];
#pragma unroll
    for (int s = 0; s < 7; s++) {
        float a = 0.f;
#pragma unroll
        for (int k = 0; k < 10; k++) a += s_sph[k * 7 + s] * s_xd[k][t];
        sk[s] = a;
    }
    long ob = (long)e * 1024 + t * 16;
#pragma unroll
    for (int j = 0; j < 16; j++) {
        float a = 0.f;
#pragma unroll
        for (int s = 0; s < 7; s++) a += s_cW[j * 7 + s] * sk[s];
        __nv_bfloat16 h, l;
        split1(a, h, l);
        rWh[ob + j] = h;
        rWl[ob + j] = l;
    }
}

// ------------------------------------------------------------------
// Fused rbf_h MLP + scatter: atom[id_a[e], c] += mnew[e,c] *
//   (rbf_h[e,:16] @ W_rbf_h[:16, c]).  Block: 64 edges x 256 cols.
// ------------------------------------------------------------------
__global__ void __launch_bounds__(256) scatter_fused(
    const float* __restrict__ mnew, const float* __restrict__ rbf_h,
    const float* __restrict__ W,   // [16][512]
    const int* __restrict__ id_a, float* __restrict__ atom, int nE)
{
    __shared__ float sW[16 * 256];
    __shared__ float srbf[64 * 16];
    __shared__ int sida[64];

    const int tid = threadIdx.x;
    const int chalf = blockIdx.y;
    const long e0 = (long)blockIdx.x * 64;

    for (int idx = tid; idx < 4096; idx += 256) {
        int t = idx >> 8, c = idx & 255;
        sW[idx] = W[t * 512 + chalf * 256 + c];
    }
    for (int idx = tid; idx < 1024; idx += 256) {
        int el = idx >> 4, t = idx & 15;
        long eg = e0 + el;
        srbf[idx] = (eg < nE) ? rbf_h[eg * 16 + t] : 0.f;
    }
    if (tid < 64) {
        long eg = e0 + tid;
        sida[tid] = (eg < nE) ? id_a[eg] : 0;
    }
    __syncthreads();

    const int c = tid;
    int nel = (int)(((long)nE - e0) < 64 ? (nE - e0) : 64);
    for (int el = 0; el < nel; el++) {
        long eg = e0 + el;
        float rw = 0.f;
#pragma unroll
        for (int t = 0; t < 16; t++) rw += srbf[el * 16 + t] * sW[t * 256 + c];
        float v = mnew[eg * 512 + chalf * 256 + c] * rw;
        atomicAdd(&atom[(long)sida[el] * 512 + chalf * 256 + c], v);
    }
}

// ------------------------------------------------------------------
// Remaining elementwise kernels
// ------------------------------------------------------------------
__global__ void zero_kernel(float* __restrict__ p, long n)
{
    long i = (long)blockIdx.x * blockDim.x + threadIdx.x;
    if (i < n) p[i] = 0.f;
}

__global__ void hnew_kernel(const float* __restrict__ h, const float* __restrict__ xa,
                            float* __restrict__ hnew, float* __restrict__ out, long n)
{
    long i = (long)blockIdx.x * blockDim.x + threadIdx.x;
    if (i >= n) return;
    float v = (h[i] + xa[i]) * INV_SQRT2;
    hnew[i] = v;
    out[i] = v;
}

__global__ void concat_kernel(const float* __restrict__ hnew, const int* __restrict__ id_c,
                              const int* __restrict__ id_a, const float* __restrict__ mnew,
                              __nv_bfloat16* __restrict__ ohi, __nv_bfloat16* __restrict__ olo, int nE)
{
    long i = (long)blockIdx.x * blockDim.x + threadIdx.x;
    long n = (long)nE * 768;
    if (i >= n) return;
    long e = i / 768;
    int k = (int)(i - e * 768);
    float v;
    if (k < 128)      v = hnew[(long)id_c[e] * A_DIM + k];
    else if (k < 256) v = hnew[(long)id_a[e] * A_DIM + (k - 128)];
    else              v = mnew[e * (long)E_DIM + (k - 256)];
    __nv_bfloat16 h, l; split1(v, h, l);
    ohi[i] = h; olo[i] = l;
}

// ------------------------------------------------------------------
// Host orchestration
// ------------------------------------------------------------------
static inline void sg(const float* A, const float* B, float* C, int M, int N, int K,
                      int flags, const float* res = nullptr)
{
    dim3 grid((N + 127) / 128, (M + 127) / 128);
    sgemm_kernel<<<grid, 256>>>(A, B, C, M, N, K, flags, res);
}

#define SMEM8 ((2 * 128 * 40 + 2 * 128 * 40) * 2 * 2)  // 81920 B
#define SMEM4 ((2 * 128 * 40 + 2 * 64 * 40) * 2 * 2)   // 61440 B

extern "C" void kernel_launch(void* const* d_in, const int* in_sizes, int n_in,
                              void* d_out, int out_size)
{
    const float* h_in       = (const float*)d_in[0];
    const float* m_in       = (const float*)d_in[1];
    const float* rbf3       = (const float*)d_in[2];
    const float* cbfW1      = (const float*)d_in[3];
    const float* sph        = (const float*)d_in[4];
    const float* rbf_h      = (const float*)d_in[5];
    const float* W_dense_ca = (const float*)d_in[6];
    const float* W_ba       = (const float*)d_in[7];
    const float* W_rbf3     = (const float*)d_in[8];
    const float* W_down     = (const float*)d_in[9];
    const float* W_bil      = (const float*)d_in[10];
    const float* W_up_ca    = (const float*)d_in[11];
    const float* W_up_ac    = (const float*)d_in[12];
    const float* W_res_b    = (const float*)d_in[13];
    const float* W_res_a    = (const float*)d_in[14];
    const float* W_rbf_hW   = (const float*)d_in[15];
    const float* W_atom_d   = (const float*)d_in[16];
    const float* W_atom_r   = (const float*)d_in[17];
    const float* W_concat   = (const float*)d_in[18];
    const float* W_res_m    = (const float*)d_in[19];
    const int* id_swap = (const int*)d_in[21];
    const int* id3_ba  = (const int*)d_in[22];
    const int* id_c    = (const int*)d_in[24];
    const int* id_a    = (const int*)d_in[25];

    int nE = in_sizes[1] / E_DIM;
    int nA = in_sizes[0] / A_DIM;
    float* out = (float*)d_out;

    float *pA, *pC, *pmnew, *pupac, *pdown;
    float *patom, *patomB, *patomC, *phnew;
    __nv_bfloat16 *H0h, *H0l, *H1h, *H1l, *wBh, *wBl;
    cudaGetSymbolAddress((void**)&pA, g_A);
    cudaGetSymbolAddress((void**)&pC, g_C);
    cudaGetSymbolAddress((void**)&pmnew, g_mnew);
    cudaGetSymbolAddress((void**)&pupac, g_upac);
    cudaGetSymbolAddress((void**)&pdown, g_down);
    cudaGetSymbolAddress((void**)&patom, g_atom);
    cudaGetSymbolAddress((void**)&patomB, g_atomB);
    cudaGetSymbolAddress((void**)&patomC, g_atomC);
    cudaGetSymbolAddress((void**)&phnew, g_hnew);
    cudaGetSymbolAddress((void**)&H0h, g_H0h);
    cudaGetSymbolAddress((void**)&H0l, g_H0l);
    cudaGetSymbolAddress((void**)&H1h, g_H1h);
    cudaGetSymbolAddress((void**)&H1l, g_H1l);
    cudaGetSymbolAddress((void**)&wBh, g_wBh);
    cudaGetSymbolAddress((void**)&wBl, g_wBl);

    cudaFuncSetAttribute(bgemm<8>, cudaFuncAttributeMaxDynamicSharedMemorySize, SMEM8);
    cudaFuncSetAttribute(bgemm<4>, cudaFuncAttributeMaxDynamicSharedMemorySize, SMEM4);

    long nME = (long)nE * E_DIM;
    int TB = 256;
    long gME = (nME + TB - 1) / TB;

    auto convW = [&](const float* W, int K, int N) {
        long n = (long)K * N;
        convertW_kernel<<<(unsigned)((n + 255) / 256), 256>>>(W, wBh, wBl, K, N);
    };
    auto tc128 = [&](const __nv_bfloat16* Ahp, const __nv_bfloat16* Alp, int M, int Nf, int K,
                     int flags, float* C, const float* res, const float* res2,
                     const float* acbuf, const int* swapidx,
                     const float* rbfA, const float* rbfWp,
                     __nv_bfloat16* Oh, __nv_bfloat16* Ol) {
        dim3 grid(Nf / 128, (M + 127) / 128);
        bgemm<8><<<grid, 256, SMEM8>>>(Ahp, Alp, wBh, wBl, M, Nf, K, flags, C, res, res2,
                                       acbuf, swapidx, rbfA, rbfWp, Oh, Ol);
    };
    auto tc64 = [&](const __nv_bfloat16* Ahp, const __nv_bfloat16* Alp, int M, int Nf, int K,
                    int flags, float* C, __nv_bfloat16* Oh, __nv_bfloat16* Ol) {
        dim3 grid(Nf / 64, (M + 127) / 128);
        bgemm<4><<<grid, 256, SMEM4>>>(Ahp, Alp, wBh, wBl, M, Nf, K, flags, C, nullptr, nullptr,
                                       nullptr, nullptr, nullptr, nullptr, Oh, Ol);
    };

    // ---- m -> H0 hi/lo ----
    convertA_kernel<<<(unsigned)gME, TB>>>(m_in, H0h, H0l, nME);
    // ---- skip branch -> pA ----
    convW(W_dense_ca, 512, 512);
    tc128(H0h, H0l, nE, 512, 512, F_ACT | F_F32, pA, nullptr, nullptr, nullptr, nullptr,
          nullptr, nullptr, nullptr, nullptr);
    // ---- x_ba = act(m@W_ba) * (rbf3@W_rbf3) -> H1 (rbf MLP fused) ----
    convW(W_ba, 512, 512);
    tc128(H0h, H0l, nE, 512, 512, F_ACT | F_RBF | F_BF, nullptr, nullptr, nullptr, nullptr,
          nullptr, rbf3, W_rbf3, H1h, H1l);
    // ---- down ----
    convW(W_down, 512, 64);
    tc64(H1h, H1l, nE, 64, 512, F_ACT | F_F32, pdown, nullptr, nullptr);
    // ---- triplet -> rW (hi/lo in H0, width 1024) ----
    triplet_kernel<<<nE, 64>>>(pdown, sph, cbfW1, id3_ba, H0h, H0l, nE);
    // ---- bilinear -> H1 (width 64) ----
    convW(W_bil, 1024, 64);
    tc64(H0h, H0l, nE, 64, 1024, F_BF, nullptr, H1h, H1l);
    // ---- up_ac (must precede fused combine) ----
    convW(W_up_ac, 64, 512);
    tc128(H1h, H1l, nE, 512, 64, F_ACT | F_F32, pupac, nullptr, nullptr, nullptr, nullptr,
          nullptr, nullptr, nullptr, nullptr);
    // ---- up_ca with fused combine -> pC + H0 ----
    convW(W_up_ca, 64, 512);
    tc128(H1h, H1l, nE, 512, 64, F_ACT | F_CMB | F_F32 | F_BF, pC, pA, nullptr, pupac, id_swap,
          nullptr, nullptr, H0h, H0l);
    // ---- residual before; 2nd GEMM fuses m_new = (m + (pC + act)*s)*s ----
    convW(W_res_b, 512, 512);
    tc128(H0h, H0l, nE, 512, 512, F_ACT | F_BF, nullptr, nullptr, nullptr, nullptr, nullptr,
          nullptr, nullptr, H1h, H1l);
    convW(W_res_b + 262144, 512, 512);
    tc128(H1h, H1l, nE, 512, 512, F_ACT | F_RES | F_RES2 | F_F32 | F_BF, pmnew, pC, m_in,
          nullptr, nullptr, nullptr, nullptr, H0h, H0l);
    // ---- residual after x2 ----
    for (int i = 0; i < 2; i++) {
        convW(W_res_a + (long)i * 2 * 262144, 512, 512);
        tc128(H0h, H0l, nE, 512, 512, F_ACT | F_BF, nullptr, nullptr, nullptr, nullptr, nullptr,
              nullptr, nullptr, H1h, H1l);
        convW(W_res_a + (long)i * 2 * 262144 + 262144, 512, 512);
        tc128(H1h, H1l, nE, 512, 512, F_ACT | F_RES | F_F32 | F_BF, pmnew, pmnew, nullptr,
              nullptr, nullptr, nullptr, nullptr, H0h, H0l);
    }
    // ---- atom update: fused rbf_h MLP + scatter ----
    long nAtomE = (long)nA * E_DIM;
    zero_kernel<<<(unsigned)((nAtomE + TB - 1) / TB), TB>>>(patom, nAtomE);
    {
        dim3 grid((nE + 63) / 64, 2);
        scatter_fused<<<grid, 256>>>(pmnew, rbf_h, W_rbf_hW, id_a, patom, nE);
    }
    sg(patom, W_atom_d, patomB, nA, A_DIM, E_DIM, F_ACT);
    for (int i = 0; i < 3; i++) {
        sg(patomB, W_atom_r + (long)i * 2 * 16384, patomC, nA, A_DIM, A_DIM, F_ACT);
        sg(patomC, W_atom_r + (long)i * 2 * 16384 + 16384, patomB, nA, A_DIM, A_DIM,
           F_ACT | F_RES, patomB);
    }
    long nAA = (long)nA * A_DIM;
    hnew_kernel<<<(unsigned)((nAA + TB - 1) / TB), TB>>>(h_in, patomB, phnew, out, nAA);
    // ---- edge embedding ----
    long nCE = (long)nE * 768;
    concat_kernel<<<(unsigned)((nCE + TB - 1) / TB), TB>>>(phnew, id_c, id_a, pmnew, H1h, H1l, nE);
    convW(W_concat, 768, 512);
    tc128(H1h, H1l, nE, 512, 768, F_ACT | F_F32 | F_BF, pA, nullptr, nullptr, nullptr, nullptr,
          nullptr, nullptr, H0h, H0l);
    convW(W_res_m, 512, 512);
    tc128(H0h, H0l, nE, 512, 512, F_ACT | F_BF, nullptr, nullptr, nullptr, nullptr, nullptr,
          nullptr, nullptr, H1h, H1l);
    // ---- last GEMM fuses m_out = (mnew + (pA + act)*s)*s -> out ----
    convW(W_res_m + 262144, 512, 512);
    tc128(H1h, H1l, nE, 512, 512, F_ACT | F_RES | F_RES2 | F_F32, out + nAA, pA, pmnew,
          nullptr, nullptr, nullptr, nullptr, nullptr, nullptr);
}